// round 9
// baseline (speedup 1.0000x reference)
#include <cuda_runtime.h>
#include <cuda_fp16.h>
#include <cstdint>
#include <math.h>

// Problem constants
#define BB 4
#define NN 4096
#define CC 1024
#define HH 16
#define MM (BB*NN)   // 16384

// ---------------- scratch (device globals; no allocation) ----------------
__device__ float g_W[(size_t)MM * CC];       // qkv projection result fp32
__device__ __half g_Ah[(size_t)MM * CC];     // fp16 of x, later of T
__device__ __half g_B1[(size_t)CC * CC];     // qkv_w fp16
__device__ __half g_B2[(size_t)CC * CC];     // out_w fp16
__device__ float g_pi[(size_t)MM * HH];
// stats: [0,BB*CC) = norm2, [BB*CC,2*BB*CC) = dots, [2*BB*CC,+BB*HH) = sumpi
__device__ float g_stats[2 * BB * CC + BB * HH];

// ---------------- PTX helpers ---------------------------------------------
__device__ __forceinline__ uint32_t smem_u32(const void* p) {
    uint32_t a;
    asm("{ .reg .u64 t; cvta.to.shared.u64 t, %1; cvt.u32.u64 %0, t; }" : "=r"(a) : "l"(p));
    return a;
}
#define CP_ASYNC16(dst, src) \
    asm volatile("cp.async.cg.shared.global [%0], [%1], 16;" :: "r"(dst), "l"(src) : "memory")
#define CP_COMMIT() asm volatile("cp.async.commit_group;" ::: "memory")
#define CP_WAIT1()  asm volatile("cp.async.wait_group 1;" ::: "memory")

__device__ __forceinline__ void ldsm4(uint32_t* r, uint32_t addr) {
    asm volatile("ldmatrix.sync.aligned.m8n8.x4.shared.b16 {%0,%1,%2,%3}, [%4];"
        : "=r"(r[0]), "=r"(r[1]), "=r"(r[2]), "=r"(r[3]) : "r"(addr));
}
__device__ __forceinline__ void mma16816(float* c, const uint32_t* a, const uint32_t* b) {
    asm volatile("mma.sync.aligned.m16n8k16.row.col.f32.f16.f16.f32 "
        "{%0,%1,%2,%3}, {%4,%5,%6,%7}, {%8,%9}, {%0,%1,%2,%3};"
        : "+f"(c[0]), "+f"(c[1]), "+f"(c[2]), "+f"(c[3])
        : "r"(a[0]), "r"(a[1]), "r"(a[2]), "r"(a[3]), "r"(b[0]), "r"(b[1]));
}

// ---------------- fp16 HMMA GEMM: C[m,n] = sum_k A[m,k]*B[n,k] (+bias) ----
// Tile 128x128, BK=64, 256 threads (warps 2m x 4n), 3-stage pipe, 2 CTAs/SM.
// smem rows: 128 fp16 = 128B, SW128 swizzle (16B chunk XOR row&7).
#define STG_BYTES 32768     // A tile 16KB + B tile 16KB
#define OFF_B 16384
#define NSTG 3

__global__ __launch_bounds__(256, 2) void gemm_fp16(
    const __half* __restrict__ A, const __half* __restrict__ B,
    const float* __restrict__ bias, float* __restrict__ C,
    float* __restrict__ norm2, int M, int N, int K)
{
    extern __shared__ __align__(1024) char smem[];
    const uint32_t sm_base = smem_u32(smem);

    const int tid  = threadIdx.x;
    const int lane = tid & 31;
    const int wid  = tid >> 5;
    const int mw   = wid >> 2;        // 0..1
    const int nw   = wid & 3;         // 0..3
    const int m0   = blockIdx.y * 128;
    const int n0   = blockIdx.x * 128;

    // ---- loader mapping: thread -> one 128B row of A or B tile ------------
    const int lrow = tid & 127;
    const int isB  = tid >> 7;        // 0 = A, 1 = B
    const uint32_t dbase = (uint32_t)(isB ? OFF_B : 0) + (uint32_t)lrow * 128;
    const uint32_t dxor  = (uint32_t)((lrow & 7) << 4);
    const char* srcRow = isB
        ? (const char*)(B + (size_t)(n0 + lrow) * K)
        : (const char*)(A + (size_t)(m0 + lrow) * K);

    const int NCHUNK = K / 64;        // 16

    auto load_stage = [&](int s, int sbuf) {
        const uint32_t sb = sm_base + (uint32_t)sbuf * STG_BYTES;
        const char* sp = srcRow + s * 128;   // 64 fp16 = 128B per chunk
        #pragma unroll
        for (int j = 0; j < 8; j++) {
            CP_ASYNC16(sb + dbase + (((uint32_t)(j * 16)) ^ dxor), sp + j * 16);
        }
        CP_COMMIT();
    };

    // ---- per-warp ldmatrix address components -----------------------------
    uint32_t aro[4], asw[4];
    #pragma unroll
    for (int mi = 0; mi < 4; mi++) {
        int row = mw * 64 + mi * 16 + (lane & 15);
        aro[mi] = (uint32_t)(row * 128);
        asw[mi] = (uint32_t)((row & 7) << 4);
    }
    const uint32_t a_kb_lane = (uint32_t)((lane >> 4) << 4);
    uint32_t bro[2], bsw[2];
    #pragma unroll
    for (int g = 0; g < 2; g++) {
        int row = nw * 32 + g * 16 + (lane & 7) + ((lane >> 4) << 3);
        bro[g] = (uint32_t)(OFF_B + row * 128);
        bsw[g] = (uint32_t)((row & 7) << 4);
    }
    const uint32_t b_kb_lane = (uint32_t)((lane & 8) << 1);

    float acc[4][4][4];
    #pragma unroll
    for (int i = 0; i < 4; i++)
        #pragma unroll
        for (int j = 0; j < 4; j++)
            #pragma unroll
            for (int q = 0; q < 4; q++) acc[i][j][q] = 0.f;

    load_stage(0, 0);
    load_stage(1, 1);

    int sbuf = 0;       // buffer of stage s
    int lbuf = 2;       // buffer for stage s+2
    for (int s = 0; s < NCHUNK; s++) {
        CP_WAIT1();
        __syncthreads();
        const uint32_t sb = sm_base + (uint32_t)sbuf * STG_BYTES;

        uint32_t fA[2][4][4], fB[2][2][4];
        auto ldfrag = [&](int ks, int pb) {
            const uint32_t akb = (uint32_t)(ks * 32) + a_kb_lane;
            const uint32_t bkb = (uint32_t)(ks * 32) + b_kb_lane;
            #pragma unroll
            for (int mi = 0; mi < 4; mi++)
                ldsm4(fA[pb][mi], sb + aro[mi] + (akb ^ asw[mi]));
            #pragma unroll
            for (int g = 0; g < 2; g++)
                ldsm4(fB[pb][g], sb + bro[g] + (bkb ^ bsw[g]));
        };

        ldfrag(0, 0);
        #pragma unroll
        for (int ks = 0; ks < 4; ks++) {
            if (ks < 3) ldfrag(ks + 1, (ks + 1) & 1);
            const int pb = ks & 1;
            #pragma unroll
            for (int mi = 0; mi < 4; mi++) {
                #pragma unroll
                for (int nj = 0; nj < 4; nj++) {
                    mma16816(acc[mi][nj], fA[pb][mi], &fB[pb][nj >> 1][(nj & 1) * 2]);
                }
            }
        }

        if (s + 2 < NCHUNK) load_stage(s + 2, lbuf);
        else CP_COMMIT();   // keep group accounting for tail waits
        sbuf = (sbuf + 1 == NSTG) ? 0 : sbuf + 1;
        lbuf = (lbuf + 1 == NSTG) ? 0 : lbuf + 1;
    }

    // ---- epilogue ---------------------------------------------------------
    const int mbase = m0 + mw * 64 + (lane >> 2);
    const int nbase = n0 + nw * 32 + 2 * (lane & 3);
    #pragma unroll
    for (int mi = 0; mi < 4; mi++) {
        #pragma unroll
        for (int nj = 0; nj < 4; nj++) {
            const int r0 = mbase + mi * 16;
            const int cc = nbase + nj * 8;
            float b0 = 0.f, b1 = 0.f;
            if (bias) { b0 = __ldg(bias + cc); b1 = __ldg(bias + cc + 1); }
            float2 v0 = make_float2(acc[mi][nj][0] + b0, acc[mi][nj][1] + b1);
            float2 v1 = make_float2(acc[mi][nj][2] + b0, acc[mi][nj][3] + b1);
            *reinterpret_cast<float2*>(C + (size_t)r0 * N + cc)       = v0;
            *reinterpret_cast<float2*>(C + (size_t)(r0 + 8) * N + cc) = v1;
        }
    }

    // ---- fused norm2: sum over this tile's 128 rows of C^2 per column -----
    if (norm2) {
        const int b = m0 >> 12;   // tile fits inside one batch (NN % 128 == 0)
        float cs[4][2];
        #pragma unroll
        for (int nj = 0; nj < 4; nj++) {
            cs[nj][0] = 0.f; cs[nj][1] = 0.f;
            #pragma unroll
            for (int mi = 0; mi < 4; mi++) {
                cs[nj][0] = fmaf(acc[mi][nj][0], acc[mi][nj][0], cs[nj][0]);
                cs[nj][0] = fmaf(acc[mi][nj][2], acc[mi][nj][2], cs[nj][0]);
                cs[nj][1] = fmaf(acc[mi][nj][1], acc[mi][nj][1], cs[nj][1]);
                cs[nj][1] = fmaf(acc[mi][nj][3], acc[mi][nj][3], cs[nj][1]);
            }
        }
        #pragma unroll
        for (int nj = 0; nj < 4; nj++) {
            #pragma unroll
            for (int t = 0; t < 2; t++) {
                float v = cs[nj][t];
                v += __shfl_xor_sync(0xffffffffu, v, 4);
                v += __shfl_xor_sync(0xffffffffu, v, 8);
                v += __shfl_xor_sync(0xffffffffu, v, 16);
                cs[nj][t] = v;
            }
        }
        if (lane < 4) {
            const int cb = n0 + nw * 32 + 2 * lane;
            #pragma unroll
            for (int nj = 0; nj < 4; nj++) {
                atomicAdd(&norm2[b * CC + cb + nj * 8],     cs[nj][0]);
                atomicAdd(&norm2[b * CC + cb + nj * 8 + 1], cs[nj][1]);
            }
        }
    }
}

// ---------------- fp32 -> fp16 cast ----------------------------------------
__global__ __launch_bounds__(256) void cast_fp16_kernel(
    const float* __restrict__ src, __half* __restrict__ dst, int n4)
{
    const int i = blockIdx.x * 256 + threadIdx.x;
    if (i >= n4) return;
    float4 v = reinterpret_cast<const float4*>(src)[i];
    __half2 h[2];
    h[0] = __halves2half2(__float2half_rn(v.x), __float2half_rn(v.y));
    h[1] = __halves2half2(__float2half_rn(v.z), __float2half_rn(v.w));
    reinterpret_cast<uint2*>(dst)[i] = *reinterpret_cast<uint2*>(h);
}

// ---------------- pi + reductions ------------------------------------------
__global__ __launch_bounds__(256) void pi_kernel(
    const float* __restrict__ W, const float* __restrict__ norm2,
    const float* __restrict__ temp,
    float* __restrict__ pi_out, float* __restrict__ dots,
    float* __restrict__ sumpi)
{
    const int tid  = threadIdx.x;
    const int m0   = blockIdx.x * 16;
    const int b    = m0 >> 12;
    const int c0   = tid * 4;
    const int h    = tid >> 4;
    const int lane = tid & 31;

    __shared__ float s_head[16];
    __shared__ float s_pi[16];

    float inv2[4];
    #pragma unroll
    for (int i = 0; i < 4; i++) {
        float nrm = sqrtf(norm2[b * CC + c0 + i]);
        float inv = 1.0f / fmaxf(nrm, 1e-12f);
        inv2[i] = inv * inv;
    }
    const float tmult = temp[h];

    float accD[4] = {0.f, 0.f, 0.f, 0.f};
    float sumPiLoc = 0.f;

    for (int r = 0; r < 16; r++) {
        const int m = m0 + r;
        float4 w4 = *reinterpret_cast<const float4*>(&W[(size_t)m * CC + c0]);
        float sq[4] = {w4.x*w4.x, w4.y*w4.y, w4.z*w4.z, w4.w*w4.w};
        float part = sq[0]*inv2[0] + sq[1]*inv2[1] + sq[2]*inv2[2] + sq[3]*inv2[3];
        part += __shfl_xor_sync(0xffffffffu, part, 8);
        part += __shfl_xor_sync(0xffffffffu, part, 4);
        part += __shfl_xor_sync(0xffffffffu, part, 2);
        part += __shfl_xor_sync(0xffffffffu, part, 1);
        if ((lane & 15) == 0) s_head[h] = part * tmult;
        __syncthreads();
        if (tid < 16) {
            float v  = s_head[tid];
            float mx = v;
            #pragma unroll
            for (int o = 8; o; o >>= 1) mx = fmaxf(mx, __shfl_xor_sync(0x0000ffffu, mx, o));
            float e  = expf(v - mx);
            float se = e;
            #pragma unroll
            for (int o = 8; o; o >>= 1) se += __shfl_xor_sync(0x0000ffffu, se, o);
            float p = e / se;
            s_pi[tid]  = p;
            sumPiLoc  += p;
            pi_out[(size_t)m * HH + tid] = p;
        }
        __syncthreads();
        const float phd = s_pi[h];
        #pragma unroll
        for (int i = 0; i < 4; i++) accD[i] = fmaf(phd, sq[i], accD[i]);
    }

    #pragma unroll
    for (int i = 0; i < 4; i++)
        atomicAdd(&dots[b * CC + c0 + i], accD[i]);
    if (tid < 16)
        atomicAdd(&sumpi[b * HH + tid], sumPiLoc);
}

// ---- gate (attn fused): T = -W * pi * (1/(1+dots/(sumpi+1e-8))) -> fp16 ---
__global__ __launch_bounds__(256) void gate_kernel(
    const float* __restrict__ W, const float* __restrict__ pi,
    const float* __restrict__ dots, const float* __restrict__ sumpi,
    __half* __restrict__ Th)
{
    const size_t idx  = (size_t)blockIdx.x * 256 + threadIdx.x;
    const size_t base = idx * 4;
    const int m = (int)(base >> 10);
    const int c = (int)(base & (CC - 1));
    const int b = m >> 12;
    const int h = c >> 6;
    float4 w4 = *reinterpret_cast<const float4*>(W + base);
    float4 d4 = *reinterpret_cast<const float4*>(dots + b * CC + c);
    const float spv = sumpi[b * HH + h] + 1e-8f;
    const float p = -pi[(size_t)m * HH + h];
    float a0 = 1.0f / (1.0f + d4.x / spv);
    float a1 = 1.0f / (1.0f + d4.y / spv);
    float a2 = 1.0f / (1.0f + d4.z / spv);
    float a3 = 1.0f / (1.0f + d4.w / spv);
    __half2 o[2];
    o[0] = __halves2half2(__float2half_rn(w4.x * p * a0),
                          __float2half_rn(w4.y * p * a1));
    o[1] = __halves2half2(__float2half_rn(w4.z * p * a2),
                          __float2half_rn(w4.w * p * a3));
    reinterpret_cast<uint2*>(Th)[idx] = *reinterpret_cast<uint2*>(o);
}

// ---------------- launch ---------------------------------------------------
extern "C" void kernel_launch(void* const* d_in, const int* in_sizes, int n_in,
                              void* d_out, int out_size)
{
    const float* x     = (const float*)d_in[0];
    const float* qkv_w = (const float*)d_in[1];
    const float* temp  = (const float*)d_in[2];
    const float* out_w = (const float*)d_in[3];
    const float* out_b = (const float*)d_in[4];
    float* y = (float*)d_out;

    float *W, *pi, *stats;
    __half *Ah, *B1, *B2;
    cudaGetSymbolAddress((void**)&W,     g_W);
    cudaGetSymbolAddress((void**)&pi,    g_pi);
    cudaGetSymbolAddress((void**)&stats, g_stats);
    cudaGetSymbolAddress((void**)&Ah,    g_Ah);
    cudaGetSymbolAddress((void**)&B1,    g_B1);
    cudaGetSymbolAddress((void**)&B2,    g_B2);
    float* nrm  = stats;
    float* dots = stats + BB * CC;
    float* sp   = stats + 2 * BB * CC;

    cudaFuncSetAttribute(gemm_fp16, cudaFuncAttributeMaxDynamicSharedMemorySize, NSTG * STG_BYTES);

    cudaMemsetAsync(stats, 0, (2 * BB * CC + BB * HH) * sizeof(float));

    const int n4_big   = (MM * CC) / 4;
    const int n4_small = (CC * CC) / 4;

    cast_fp16_kernel<<<n4_big / 256, 256>>>(x, Ah, n4_big);
    cast_fp16_kernel<<<n4_small / 256, 256>>>(qkv_w, B1, n4_small);
    cast_fp16_kernel<<<n4_small / 256, 256>>>(out_w, B2, n4_small);

    dim3 ggrid(CC / 128, MM / 128);   // (8, 128)

    // 1) W = x @ qkv_w^T (fp16 HMMA) + fused norm2
    gemm_fp16<<<ggrid, 256, NSTG * STG_BYTES>>>(Ah, B1, nullptr, W, nrm, MM, CC, CC);
    // 2) stats
    pi_kernel<<<MM / 16, 256>>>(W, nrm, temp, pi, dots, sp);
    // 3) gate (attn fused) -> fp16 (reuses Ah)
    gate_kernel<<<(int)(((size_t)MM * CC / 4) / 256), 256>>>(W, pi, dots, sp, Ah);
    // 4) y = T @ out_w^T + out_b
    gemm_fp16<<<ggrid, 256, NSTG * STG_BYTES>>>(Ah, B2, out_b, y, nullptr, MM, CC, CC);
}

// round 10
// speedup vs baseline: 1.4833x; 1.4833x over previous
#include <cuda_runtime.h>
#include <cuda_fp16.h>
#include <cstdint>
#include <math.h>

// Problem constants
#define BB 4
#define NN 4096
#define CC 1024
#define HH 16
#define MM (BB*NN)   // 16384

// ---------------- scratch (device globals; no allocation) ----------------
__device__ float g_W[(size_t)MM * CC];       // qkv projection result fp32
__device__ __half g_Ah[(size_t)MM * CC];     // fp16 of x, later of T
__device__ __half g_B1[(size_t)CC * CC];     // qkv_w fp16
__device__ __half g_B2[(size_t)CC * CC];     // out_w fp16
__device__ float g_pi[(size_t)MM * HH];
// stats: [0,BB*CC) = norm2, [BB*CC,2*BB*CC) = dots, [2*BB*CC,+BB*HH) = sumpi
__device__ float g_stats[2 * BB * CC + BB * HH];

// ---------------- PTX helpers ---------------------------------------------
__device__ __forceinline__ uint32_t smem_u32(const void* p) {
    uint32_t a;
    asm("{ .reg .u64 t; cvta.to.shared.u64 t, %1; cvt.u32.u64 %0, t; }" : "=r"(a) : "l"(p));
    return a;
}
#define CP_ASYNC16(dst, src) \
    asm volatile("cp.async.cg.shared.global [%0], [%1], 16;" :: "r"(dst), "l"(src) : "memory")
#define CP_COMMIT() asm volatile("cp.async.commit_group;" ::: "memory")
#define CP_WAIT2()  asm volatile("cp.async.wait_group 2;" ::: "memory")

__device__ __forceinline__ void ldsm4(uint32_t* r, uint32_t addr) {
    asm volatile("ldmatrix.sync.aligned.m8n8.x4.shared.b16 {%0,%1,%2,%3}, [%4];"
        : "=r"(r[0]), "=r"(r[1]), "=r"(r[2]), "=r"(r[3]) : "r"(addr));
}
__device__ __forceinline__ void mma16816(float* c, const uint32_t* a, const uint32_t* b) {
    asm volatile("mma.sync.aligned.m16n8k16.row.col.f32.f16.f16.f32 "
        "{%0,%1,%2,%3}, {%4,%5,%6,%7}, {%8,%9}, {%0,%1,%2,%3};"
        : "+f"(c[0]), "+f"(c[1]), "+f"(c[2]), "+f"(c[3])
        : "r"(a[0]), "r"(a[1]), "r"(a[2]), "r"(a[3]), "r"(b[0]), "r"(b[1]));
}

// smem tile: 128 rows x 32 fp16 (64B/row). Swizzle 16B chunks by ((row>>1)&3)<<4.
__device__ __forceinline__ uint32_t tswz(int row, int kb) {
    return (uint32_t)(row * 64 + (kb ^ (((row >> 1) & 3) << 4)));
}

// ---------------- fp16 HMMA GEMM: C[m,n] = sum_k A[m,k]*B[n,k] (+bias) ----
// Tile 128x128, BK=32, 256 threads (warps 2m x 4n, 64x32 each), 4-stage pipe.
// 2 CTAs/SM (regs capped at 128, 64KB smem per CTA).
#define STG_BYTES 16384     // 2 sub-tiles x 8KB per stage
#define OFF_A  0
#define OFF_B  8192
#define NSTG 4

__global__ __launch_bounds__(256, 2) void gemm_fp16(
    const __half* __restrict__ A, const __half* __restrict__ B,
    const float* __restrict__ bias, float* __restrict__ C,
    float* __restrict__ norm2, int M, int N, int K)
{
    extern __shared__ __align__(1024) char smem[];
    const uint32_t sm_base = smem_u32(smem);

    const int tid  = threadIdx.x;
    const int lane = tid & 31;
    const int wid  = tid >> 5;
    const int mw   = wid >> 2;        // 0..1
    const int nw   = wid & 3;         // 0..3
    const int m0   = blockIdx.y * 128;
    const int n0   = blockIdx.x * 128;

    // ---- loader mapping: thread -> (row, 16B chunk) -----------------------
    const int lrow = tid >> 2;        // 0..63
    const int lk16 = tid & 3;         // 0..3
    const uint32_t dst_off0 = tswz(lrow,      lk16 * 16);
    const uint32_t dst_off1 = tswz(lrow + 64, lk16 * 16);
    const char* srcA0 = (const char*)(A + (size_t)(m0 + lrow)      * K) + lk16 * 16;
    const char* srcA1 = (const char*)(A + (size_t)(m0 + lrow + 64) * K) + lk16 * 16;
    const char* srcB0 = (const char*)(B + (size_t)(n0 + lrow)      * K) + lk16 * 16;
    const char* srcB1 = (const char*)(B + (size_t)(n0 + lrow + 64) * K) + lk16 * 16;

    const int NCHUNK = K / 32;        // 32

    auto load_stage = [&](int s) {
        const uint32_t sb = sm_base + (uint32_t)(s & (NSTG - 1)) * STG_BYTES;
        const int kb = s * 64;        // byte offset along K
        CP_ASYNC16(sb + OFF_A + dst_off0, srcA0 + kb);
        CP_ASYNC16(sb + OFF_A + dst_off1, srcA1 + kb);
        CP_ASYNC16(sb + OFF_B + dst_off0, srcB0 + kb);
        CP_ASYNC16(sb + OFF_B + dst_off1, srcB1 + kb);
        CP_COMMIT();
    };

    // ---- per-warp ldmatrix address components -----------------------------
    uint32_t a_row_off[4];
    #pragma unroll
    for (int mi = 0; mi < 4; mi++) {
        int row = mw * 64 + mi * 16 + (lane & 15);
        a_row_off[mi] = (uint32_t)(row * 64);
        a_row_off[mi] |= ((uint32_t)(((row >> 1) & 3) << 4)) << 16;
    }
    const uint32_t a_kb_lane = (uint32_t)((lane >> 4) << 4);
    uint32_t b_row_off[2];
    #pragma unroll
    for (int g = 0; g < 2; g++) {
        int row = nw * 32 + g * 16 + (lane & 7) + ((lane >> 4) << 3);
        b_row_off[g] = (uint32_t)(row * 64);
        b_row_off[g] |= ((uint32_t)(((row >> 1) & 3) << 4)) << 16;
    }
    const uint32_t b_kb_lane = (uint32_t)((lane & 8) << 1);

    float acc[4][4][4];
    #pragma unroll
    for (int i = 0; i < 4; i++)
        #pragma unroll
        for (int j = 0; j < 4; j++)
            #pragma unroll
            for (int q = 0; q < 4; q++) acc[i][j][q] = 0.f;

    load_stage(0);
    load_stage(1);
    load_stage(2);

    for (int s = 0; s < NCHUNK; s++) {
        CP_WAIT2();
        __syncthreads();
        // issue next stage load EARLY: buffer (s+3)&3 == (s-1)&3, fully
        // consumed before the barrier above, so this is race-free and
        // overlaps the DMA with this chunk's MMA work.
        if (s + 3 < NCHUNK) load_stage(s + 3);
        else CP_COMMIT();   // keep group count invariant for the tail waits

        const uint32_t sb = sm_base + (uint32_t)(s & (NSTG - 1)) * STG_BYTES;

        #pragma unroll
        for (int ks = 0; ks < 2; ks++) {
            const uint32_t akb = (uint32_t)(ks * 32) + a_kb_lane;
            const uint32_t bkb = (uint32_t)(ks * 32) + b_kb_lane;
            uint32_t fA[4][4], fB[2][4];
            #pragma unroll
            for (int mi = 0; mi < 4; mi++) {
                uint32_t ro = a_row_off[mi] & 0xFFFFu;
                uint32_t sw = a_row_off[mi] >> 16;
                ldsm4(fA[mi], sb + OFF_A + ro + (akb ^ sw));
            }
            #pragma unroll
            for (int g = 0; g < 2; g++) {
                uint32_t ro = b_row_off[g] & 0xFFFFu;
                uint32_t sw = b_row_off[g] >> 16;
                ldsm4(fB[g], sb + OFF_B + ro + (bkb ^ sw));
            }
            #pragma unroll
            for (int mi = 0; mi < 4; mi++) {
                #pragma unroll
                for (int nj = 0; nj < 4; nj++) {
                    mma16816(acc[mi][nj], fA[mi], &fB[nj >> 1][(nj & 1) * 2]);
                }
            }
        }
    }

    // ---- epilogue ---------------------------------------------------------
    const int mbase = m0 + mw * 64 + (lane >> 2);
    const int nbase = n0 + nw * 32 + 2 * (lane & 3);
    #pragma unroll
    for (int mi = 0; mi < 4; mi++) {
        #pragma unroll
        for (int nj = 0; nj < 4; nj++) {
            const int r0 = mbase + mi * 16;
            const int cc = nbase + nj * 8;
            float b0 = 0.f, b1 = 0.f;
            if (bias) { b0 = __ldg(bias + cc); b1 = __ldg(bias + cc + 1); }
            float2 v0 = make_float2(acc[mi][nj][0] + b0, acc[mi][nj][1] + b1);
            float2 v1 = make_float2(acc[mi][nj][2] + b0, acc[mi][nj][3] + b1);
            *reinterpret_cast<float2*>(C + (size_t)r0 * N + cc)       = v0;
            *reinterpret_cast<float2*>(C + (size_t)(r0 + 8) * N + cc) = v1;
        }
    }

    // ---- fused norm2: sum over this tile's 128 rows of C^2 per column -----
    if (norm2) {
        const int b = m0 >> 12;   // tile fits inside one batch (NN % 128 == 0)
        float cs[4][2];
        #pragma unroll
        for (int nj = 0; nj < 4; nj++) {
            cs[nj][0] = 0.f; cs[nj][1] = 0.f;
            #pragma unroll
            for (int mi = 0; mi < 4; mi++) {
                cs[nj][0] = fmaf(acc[mi][nj][0], acc[mi][nj][0], cs[nj][0]);
                cs[nj][0] = fmaf(acc[mi][nj][2], acc[mi][nj][2], cs[nj][0]);
                cs[nj][1] = fmaf(acc[mi][nj][1], acc[mi][nj][1], cs[nj][1]);
                cs[nj][1] = fmaf(acc[mi][nj][3], acc[mi][nj][3], cs[nj][1]);
            }
        }
        #pragma unroll
        for (int nj = 0; nj < 4; nj++) {
            #pragma unroll
            for (int t = 0; t < 2; t++) {
                float v = cs[nj][t];
                v += __shfl_xor_sync(0xffffffffu, v, 4);
                v += __shfl_xor_sync(0xffffffffu, v, 8);
                v += __shfl_xor_sync(0xffffffffu, v, 16);
                cs[nj][t] = v;
            }
        }
        if (lane < 4) {
            const int cb = n0 + nw * 32 + 2 * lane;
            #pragma unroll
            for (int nj = 0; nj < 4; nj++) {
                atomicAdd(&norm2[b * CC + cb + nj * 8],     cs[nj][0]);
                atomicAdd(&norm2[b * CC + cb + nj * 8 + 1], cs[nj][1]);
            }
        }
    }
}

// ---------------- fp32 -> fp16 cast ----------------------------------------
__global__ __launch_bounds__(256) void cast_fp16_kernel(
    const float* __restrict__ src, __half* __restrict__ dst, int n4)
{
    const int i = blockIdx.x * 256 + threadIdx.x;
    if (i >= n4) return;
    float4 v = reinterpret_cast<const float4*>(src)[i];
    __half2 h[2];
    h[0] = __halves2half2(__float2half_rn(v.x), __float2half_rn(v.y));
    h[1] = __halves2half2(__float2half_rn(v.z), __float2half_rn(v.w));
    reinterpret_cast<uint2*>(dst)[i] = *reinterpret_cast<uint2*>(h);
}

// ---------------- pi + reductions ------------------------------------------
__global__ __launch_bounds__(256) void pi_kernel(
    const float* __restrict__ W, const float* __restrict__ norm2,
    const float* __restrict__ temp,
    float* __restrict__ pi_out, float* __restrict__ dots,
    float* __restrict__ sumpi)
{
    const int tid  = threadIdx.x;
    const int m0   = blockIdx.x * 16;
    const int b    = m0 >> 12;
    const int c0   = tid * 4;
    const int h    = tid >> 4;
    const int lane = tid & 31;

    __shared__ float s_head[16];
    __shared__ float s_pi[16];

    float inv2[4];
    #pragma unroll
    for (int i = 0; i < 4; i++) {
        float nrm = sqrtf(norm2[b * CC + c0 + i]);
        float inv = 1.0f / fmaxf(nrm, 1e-12f);
        inv2[i] = inv * inv;
    }
    const float tmult = temp[h];

    float accD[4] = {0.f, 0.f, 0.f, 0.f};
    float sumPiLoc = 0.f;

    for (int r = 0; r < 16; r++) {
        const int m = m0 + r;
        float4 w4 = *reinterpret_cast<const float4*>(&W[(size_t)m * CC + c0]);
        float sq[4] = {w4.x*w4.x, w4.y*w4.y, w4.z*w4.z, w4.w*w4.w};
        float part = sq[0]*inv2[0] + sq[1]*inv2[1] + sq[2]*inv2[2] + sq[3]*inv2[3];
        part += __shfl_xor_sync(0xffffffffu, part, 8);
        part += __shfl_xor_sync(0xffffffffu, part, 4);
        part += __shfl_xor_sync(0xffffffffu, part, 2);
        part += __shfl_xor_sync(0xffffffffu, part, 1);
        if ((lane & 15) == 0) s_head[h] = part * tmult;
        __syncthreads();
        if (tid < 16) {
            float v  = s_head[tid];
            float mx = v;
            #pragma unroll
            for (int o = 8; o; o >>= 1) mx = fmaxf(mx, __shfl_xor_sync(0x0000ffffu, mx, o));
            float e  = expf(v - mx);
            float se = e;
            #pragma unroll
            for (int o = 8; o; o >>= 1) se += __shfl_xor_sync(0x0000ffffu, se, o);
            float p = e / se;
            s_pi[tid]  = p;
            sumPiLoc  += p;
            pi_out[(size_t)m * HH + tid] = p;
        }
        __syncthreads();
        const float phd = s_pi[h];
        #pragma unroll
        for (int i = 0; i < 4; i++) accD[i] = fmaf(phd, sq[i], accD[i]);
    }

    #pragma unroll
    for (int i = 0; i < 4; i++)
        atomicAdd(&dots[b * CC + c0 + i], accD[i]);
    if (tid < 16)
        atomicAdd(&sumpi[b * HH + tid], sumPiLoc);
}

// ---- gate (attn fused): T = -W * pi * (1/(1+dots/(sumpi+1e-8))) -> fp16 ---
__global__ __launch_bounds__(256) void gate_kernel(
    const float* __restrict__ W, const float* __restrict__ pi,
    const float* __restrict__ dots, const float* __restrict__ sumpi,
    __half* __restrict__ Th)
{
    const size_t idx  = (size_t)blockIdx.x * 256 + threadIdx.x;
    const size_t base = idx * 4;
    const int m = (int)(base >> 10);
    const int c = (int)(base & (CC - 1));
    const int b = m >> 12;
    const int h = c >> 6;
    float4 w4 = *reinterpret_cast<const float4*>(W + base);
    float4 d4 = *reinterpret_cast<const float4*>(dots + b * CC + c);
    const float spv = sumpi[b * HH + h] + 1e-8f;
    const float p = -pi[(size_t)m * HH + h];
    float a0 = 1.0f / (1.0f + d4.x / spv);
    float a1 = 1.0f / (1.0f + d4.y / spv);
    float a2 = 1.0f / (1.0f + d4.z / spv);
    float a3 = 1.0f / (1.0f + d4.w / spv);
    __half2 o[2];
    o[0] = __halves2half2(__float2half_rn(w4.x * p * a0),
                          __float2half_rn(w4.y * p * a1));
    o[1] = __halves2half2(__float2half_rn(w4.z * p * a2),
                          __float2half_rn(w4.w * p * a3));
    reinterpret_cast<uint2*>(Th)[idx] = *reinterpret_cast<uint2*>(o);
}

// ---------------- launch ---------------------------------------------------
extern "C" void kernel_launch(void* const* d_in, const int* in_sizes, int n_in,
                              void* d_out, int out_size)
{
    const float* x     = (const float*)d_in[0];
    const float* qkv_w = (const float*)d_in[1];
    const float* temp  = (const float*)d_in[2];
    const float* out_w = (const float*)d_in[3];
    const float* out_b = (const float*)d_in[4];
    float* y = (float*)d_out;

    float *W, *pi, *stats;
    __half *Ah, *B1, *B2;
    cudaGetSymbolAddress((void**)&W,     g_W);
    cudaGetSymbolAddress((void**)&pi,    g_pi);
    cudaGetSymbolAddress((void**)&stats, g_stats);
    cudaGetSymbolAddress((void**)&Ah,    g_Ah);
    cudaGetSymbolAddress((void**)&B1,    g_B1);
    cudaGetSymbolAddress((void**)&B2,    g_B2);
    float* nrm  = stats;
    float* dots = stats + BB * CC;
    float* sp   = stats + 2 * BB * CC;

    cudaFuncSetAttribute(gemm_fp16, cudaFuncAttributeMaxDynamicSharedMemorySize, NSTG * STG_BYTES);

    cudaMemsetAsync(stats, 0, (2 * BB * CC + BB * HH) * sizeof(float));

    const int n4_big   = (MM * CC) / 4;
    const int n4_small = (CC * CC) / 4;

    cast_fp16_kernel<<<n4_big / 256, 256>>>(x, Ah, n4_big);
    cast_fp16_kernel<<<n4_small / 256, 256>>>(qkv_w, B1, n4_small);
    cast_fp16_kernel<<<n4_small / 256, 256>>>(out_w, B2, n4_small);

    dim3 ggrid(CC / 128, MM / 128);   // (8, 128)

    // 1) W = x @ qkv_w^T (fp16 HMMA) + fused norm2
    gemm_fp16<<<ggrid, 256, NSTG * STG_BYTES>>>(Ah, B1, nullptr, W, nrm, MM, CC, CC);
    // 2) stats
    pi_kernel<<<MM / 16, 256>>>(W, nrm, temp, pi, dots, sp);
    // 3) gate (attn fused) -> fp16 (reuses Ah)
    gate_kernel<<<(int)(((size_t)MM * CC / 4) / 256), 256>>>(W, pi, dots, sp, Ah);
    // 4) y = T @ out_w^T + out_b
    gemm_fp16<<<ggrid, 256, NSTG * STG_BYTES>>>(Ah, B2, out_b, y, nullptr, MM, CC, CC);
}

// round 12
// speedup vs baseline: 1.5407x; 1.0387x over previous
#include <cuda_runtime.h>
#include <cuda_fp16.h>
#include <cstdint>
#include <math.h>

// Problem constants
#define BB 4
#define NN 4096
#define CC 1024
#define HH 16
#define MM (BB*NN)   // 16384

// ---------------- scratch (device globals; no allocation) ----------------
__device__ __half g_Wh[(size_t)MM * CC];     // qkv projection result fp16
__device__ __half g_Ah[(size_t)MM * CC];     // fp16 of x, later of T
__device__ __half g_B1[(size_t)CC * CC];     // qkv_w fp16
__device__ __half g_B2[(size_t)CC * CC];     // out_w fp16
__device__ float g_pi[(size_t)MM * HH];
// stats: [0,BB*CC) = norm2, [BB*CC,2*BB*CC) = dots, [2*BB*CC,+BB*HH) = sumpi
__device__ float g_stats[2 * BB * CC + BB * HH];

// ---------------- PTX helpers ---------------------------------------------
__device__ __forceinline__ uint32_t smem_u32(const void* p) {
    uint32_t a;
    asm("{ .reg .u64 t; cvta.to.shared.u64 t, %1; cvt.u32.u64 %0, t; }" : "=r"(a) : "l"(p));
    return a;
}
#define CP_ASYNC16(dst, src) \
    asm volatile("cp.async.cg.shared.global [%0], [%1], 16;" :: "r"(dst), "l"(src) : "memory")
#define CP_COMMIT() asm volatile("cp.async.commit_group;" ::: "memory")
#define CP_WAIT2()  asm volatile("cp.async.wait_group 2;" ::: "memory")

__device__ __forceinline__ void ldsm4(uint32_t* r, uint32_t addr) {
    asm volatile("ldmatrix.sync.aligned.m8n8.x4.shared.b16 {%0,%1,%2,%3}, [%4];"
        : "=r"(r[0]), "=r"(r[1]), "=r"(r[2]), "=r"(r[3]) : "r"(addr));
}
__device__ __forceinline__ void mma16816(float* c, const uint32_t* a, const uint32_t* b) {
    asm volatile("mma.sync.aligned.m16n8k16.row.col.f32.f16.f16.f32 "
        "{%0,%1,%2,%3}, {%4,%5,%6,%7}, {%8,%9}, {%0,%1,%2,%3};"
        : "+f"(c[0]), "+f"(c[1]), "+f"(c[2]), "+f"(c[3])
        : "r"(a[0]), "r"(a[1]), "r"(a[2]), "r"(a[3]), "r"(b[0]), "r"(b[1]));
}

// smem tile: 128 rows x 32 fp16 (64B/row). Swizzle 16B chunks by ((row>>1)&3)<<4.
__device__ __forceinline__ uint32_t tswz(int row, int kb) {
    return (uint32_t)(row * 64 + (kb ^ (((row >> 1) & 3) << 4)));
}

// ---------------- fp16 HMMA GEMM: C[m,n] = sum_k A[m,k]*B[n,k] (+bias) ----
// Tile 128x128, BK=32, 256 threads (warps 2m x 4n, 64x32 each), 4-stage pipe.
// 2 CTAs/SM (regs capped at 128, 64KB smem per CTA).
// Output: fp32 (Cf, with bias) OR fp16 (Ch) — exactly one non-null.
#define STG_BYTES 16384     // 2 sub-tiles x 8KB per stage
#define OFF_A  0
#define OFF_B  8192
#define NSTG 4

__global__ __launch_bounds__(256, 2) void gemm_fp16(
    const __half* __restrict__ A, const __half* __restrict__ B,
    const float* __restrict__ bias, float* __restrict__ Cf,
    __half* __restrict__ Ch, float* __restrict__ norm2,
    int M, int N, int K)
{
    extern __shared__ __align__(1024) char smem[];
    const uint32_t sm_base = smem_u32(smem);

    const int tid  = threadIdx.x;
    const int lane = tid & 31;
    const int wid  = tid >> 5;
    const int mw   = wid >> 2;        // 0..1
    const int nw   = wid & 3;         // 0..3
    const int m0   = blockIdx.y * 128;
    const int n0   = blockIdx.x * 128;

    // ---- loader mapping: thread -> (row, 16B chunk) -----------------------
    const int lrow = tid >> 2;        // 0..63
    const int lk16 = tid & 3;         // 0..3
    const uint32_t dst_off0 = tswz(lrow,      lk16 * 16);
    const uint32_t dst_off1 = tswz(lrow + 64, lk16 * 16);
    const char* srcA0 = (const char*)(A + (size_t)(m0 + lrow)      * K) + lk16 * 16;
    const char* srcA1 = (const char*)(A + (size_t)(m0 + lrow + 64) * K) + lk16 * 16;
    const char* srcB0 = (const char*)(B + (size_t)(n0 + lrow)      * K) + lk16 * 16;
    const char* srcB1 = (const char*)(B + (size_t)(n0 + lrow + 64) * K) + lk16 * 16;

    const int NCHUNK = K / 32;        // 32

    auto load_stage = [&](int s) {
        const uint32_t sb = sm_base + (uint32_t)(s & (NSTG - 1)) * STG_BYTES;
        const int kb = s * 64;        // byte offset along K
        CP_ASYNC16(sb + OFF_A + dst_off0, srcA0 + kb);
        CP_ASYNC16(sb + OFF_A + dst_off1, srcA1 + kb);
        CP_ASYNC16(sb + OFF_B + dst_off0, srcB0 + kb);
        CP_ASYNC16(sb + OFF_B + dst_off1, srcB1 + kb);
        CP_COMMIT();
    };

    // ---- per-warp ldmatrix address components -----------------------------
    uint32_t a_row_off[4];
    #pragma unroll
    for (int mi = 0; mi < 4; mi++) {
        int row = mw * 64 + mi * 16 + (lane & 15);
        a_row_off[mi] = (uint32_t)(row * 64);
        a_row_off[mi] |= ((uint32_t)(((row >> 1) & 3) << 4)) << 16;
    }
    const uint32_t a_kb_lane = (uint32_t)((lane >> 4) << 4);
    uint32_t b_row_off[2];
    #pragma unroll
    for (int g = 0; g < 2; g++) {
        int row = nw * 32 + g * 16 + (lane & 7) + ((lane >> 4) << 3);
        b_row_off[g] = (uint32_t)(row * 64);
        b_row_off[g] |= ((uint32_t)(((row >> 1) & 3) << 4)) << 16;
    }
    const uint32_t b_kb_lane = (uint32_t)((lane & 8) << 1);

    float acc[4][4][4];
    #pragma unroll
    for (int i = 0; i < 4; i++)
        #pragma unroll
        for (int j = 0; j < 4; j++)
            #pragma unroll
            for (int q = 0; q < 4; q++) acc[i][j][q] = 0.f;

    load_stage(0);
    load_stage(1);
    load_stage(2);

    for (int s = 0; s < NCHUNK; s++) {
        CP_WAIT2();
        __syncthreads();
        const uint32_t sb = sm_base + (uint32_t)(s & (NSTG - 1)) * STG_BYTES;

        #pragma unroll
        for (int ks = 0; ks < 2; ks++) {
            const uint32_t akb = (uint32_t)(ks * 32) + a_kb_lane;
            const uint32_t bkb = (uint32_t)(ks * 32) + b_kb_lane;
            uint32_t fA[4][4], fB[2][4];
            #pragma unroll
            for (int mi = 0; mi < 4; mi++) {
                uint32_t ro = a_row_off[mi] & 0xFFFFu;
                uint32_t sw = a_row_off[mi] >> 16;
                ldsm4(fA[mi], sb + OFF_A + ro + (akb ^ sw));
            }
            #pragma unroll
            for (int g = 0; g < 2; g++) {
                uint32_t ro = b_row_off[g] & 0xFFFFu;
                uint32_t sw = b_row_off[g] >> 16;
                ldsm4(fB[g], sb + OFF_B + ro + (bkb ^ sw));
            }
            #pragma unroll
            for (int mi = 0; mi < 4; mi++) {
                #pragma unroll
                for (int nj = 0; nj < 4; nj++) {
                    mma16816(acc[mi][nj], fA[mi], &fB[nj >> 1][(nj & 1) * 2]);
                }
            }
        }
        if (s + 3 < NCHUNK) load_stage(s + 3);
        else CP_COMMIT();   // keep group count invariant for the tail waits
    }

    // ---- epilogue ---------------------------------------------------------
    const int mbase = m0 + mw * 64 + (lane >> 2);
    const int nbase = n0 + nw * 32 + 2 * (lane & 3);
    if (Ch) {
        #pragma unroll
        for (int mi = 0; mi < 4; mi++) {
            #pragma unroll
            for (int nj = 0; nj < 4; nj++) {
                const int r0 = mbase + mi * 16;
                const int cc = nbase + nj * 8;
                __half2 v0 = __floats2half2_rn(acc[mi][nj][0], acc[mi][nj][1]);
                __half2 v1 = __floats2half2_rn(acc[mi][nj][2], acc[mi][nj][3]);
                *reinterpret_cast<__half2*>(Ch + (size_t)r0 * N + cc)       = v0;
                *reinterpret_cast<__half2*>(Ch + (size_t)(r0 + 8) * N + cc) = v1;
            }
        }
    } else {
        #pragma unroll
        for (int mi = 0; mi < 4; mi++) {
            #pragma unroll
            for (int nj = 0; nj < 4; nj++) {
                const int r0 = mbase + mi * 16;
                const int cc = nbase + nj * 8;
                float b0 = 0.f, b1 = 0.f;
                if (bias) { b0 = __ldg(bias + cc); b1 = __ldg(bias + cc + 1); }
                float2 v0 = make_float2(acc[mi][nj][0] + b0, acc[mi][nj][1] + b1);
                float2 v1 = make_float2(acc[mi][nj][2] + b0, acc[mi][nj][3] + b1);
                *reinterpret_cast<float2*>(Cf + (size_t)r0 * N + cc)       = v0;
                *reinterpret_cast<float2*>(Cf + (size_t)(r0 + 8) * N + cc) = v1;
            }
        }
    }

    // ---- fused norm2: sum over this tile's 128 rows of C^2 per column -----
    if (norm2) {
        const int b = m0 >> 12;   // tile fits inside one batch (NN % 128 == 0)
        float cs[4][2];
        #pragma unroll
        for (int nj = 0; nj < 4; nj++) {
            cs[nj][0] = 0.f; cs[nj][1] = 0.f;
            #pragma unroll
            for (int mi = 0; mi < 4; mi++) {
                cs[nj][0] = fmaf(acc[mi][nj][0], acc[mi][nj][0], cs[nj][0]);
                cs[nj][0] = fmaf(acc[mi][nj][2], acc[mi][nj][2], cs[nj][0]);
                cs[nj][1] = fmaf(acc[mi][nj][1], acc[mi][nj][1], cs[nj][1]);
                cs[nj][1] = fmaf(acc[mi][nj][3], acc[mi][nj][3], cs[nj][1]);
            }
        }
        #pragma unroll
        for (int nj = 0; nj < 4; nj++) {
            #pragma unroll
            for (int t = 0; t < 2; t++) {
                float v = cs[nj][t];
                v += __shfl_xor_sync(0xffffffffu, v, 4);
                v += __shfl_xor_sync(0xffffffffu, v, 8);
                v += __shfl_xor_sync(0xffffffffu, v, 16);
                cs[nj][t] = v;
            }
        }
        if (lane < 4) {
            const int cb = n0 + nw * 32 + 2 * lane;
            #pragma unroll
            for (int nj = 0; nj < 4; nj++) {
                atomicAdd(&norm2[b * CC + cb + nj * 8],     cs[nj][0]);
                atomicAdd(&norm2[b * CC + cb + nj * 8 + 1], cs[nj][1]);
            }
        }
    }
}

// ---------------- fp32 -> fp16 cast ----------------------------------------
__global__ __launch_bounds__(256) void cast_fp16_kernel(
    const float* __restrict__ src, __half* __restrict__ dst, int n4)
{
    const int i = blockIdx.x * 256 + threadIdx.x;
    if (i >= n4) return;
    float4 v = reinterpret_cast<const float4*>(src)[i];
    __half2 h[2];
    h[0] = __halves2half2(__float2half_rn(v.x), __float2half_rn(v.y));
    h[1] = __halves2half2(__float2half_rn(v.z), __float2half_rn(v.w));
    reinterpret_cast<uint2*>(dst)[i] = *reinterpret_cast<uint2*>(h);
}

// ---------------- pi + reductions (reads fp16 W) ---------------------------
__global__ __launch_bounds__(256) void pi_kernel(
    const __half* __restrict__ Wh, const float* __restrict__ norm2,
    const float* __restrict__ temp,
    float* __restrict__ pi_out, float* __restrict__ dots,
    float* __restrict__ sumpi)
{
    const int tid  = threadIdx.x;
    const int m0   = blockIdx.x * 16;
    const int b    = m0 >> 12;
    const int c0   = tid * 4;
    const int h    = tid >> 4;
    const int lane = tid & 31;

    __shared__ float s_head[16];
    __shared__ float s_pi[16];

    float inv2[4];
    #pragma unroll
    for (int i = 0; i < 4; i++) {
        float nrm = sqrtf(norm2[b * CC + c0 + i]);
        float inv = 1.0f / fmaxf(nrm, 1e-12f);
        inv2[i] = inv * inv;
    }
    const float tmult = temp[h];

    float accD[4] = {0.f, 0.f, 0.f, 0.f};
    float sumPiLoc = 0.f;

    for (int r = 0; r < 16; r++) {
        const int m = m0 + r;
        uint2 raw = *reinterpret_cast<const uint2*>(&Wh[(size_t)m * CC + c0]);
        float2 w01 = __half22float2(*reinterpret_cast<__half2*>(&raw.x));
        float2 w23 = __half22float2(*reinterpret_cast<__half2*>(&raw.y));
        float sq[4] = {w01.x*w01.x, w01.y*w01.y, w23.x*w23.x, w23.y*w23.y};
        float part = sq[0]*inv2[0] + sq[1]*inv2[1] + sq[2]*inv2[2] + sq[3]*inv2[3];
        part += __shfl_xor_sync(0xffffffffu, part, 8);
        part += __shfl_xor_sync(0xffffffffu, part, 4);
        part += __shfl_xor_sync(0xffffffffu, part, 2);
        part += __shfl_xor_sync(0xffffffffu, part, 1);
        if ((lane & 15) == 0) s_head[h] = part * tmult;
        __syncthreads();
        if (tid < 16) {
            float v  = s_head[tid];
            float mx = v;
            #pragma unroll
            for (int o = 8; o; o >>= 1) mx = fmaxf(mx, __shfl_xor_sync(0x0000ffffu, mx, o));
            float e  = expf(v - mx);
            float se = e;
            #pragma unroll
            for (int o = 8; o; o >>= 1) se += __shfl_xor_sync(0x0000ffffu, se, o);
            float p = e / se;
            s_pi[tid]  = p;
            sumPiLoc  += p;
            pi_out[(size_t)m * HH + tid] = p;
        }
        __syncthreads();
        const float phd = s_pi[h];
        #pragma unroll
        for (int i = 0; i < 4; i++) accD[i] = fmaf(phd, sq[i], accD[i]);
    }

    #pragma unroll
    for (int i = 0; i < 4; i++)
        atomicAdd(&dots[b * CC + c0 + i], accD[i]);
    if (tid < 16)
        atomicAdd(&sumpi[b * HH + tid], sumPiLoc);
}

// ---- gate (attn fused): T = -W * pi * (1/(1+dots/(sumpi+1e-8))) -> fp16 ---
__global__ __launch_bounds__(256) void gate_kernel(
    const __half* __restrict__ Wh, const float* __restrict__ pi,
    const float* __restrict__ dots, const float* __restrict__ sumpi,
    __half* __restrict__ Th)
{
    const size_t idx  = (size_t)blockIdx.x * 256 + threadIdx.x;
    const size_t base = idx * 4;
    const int m = (int)(base >> 10);
    const int c = (int)(base & (CC - 1));
    const int b = m >> 12;
    const int h = c >> 6;
    uint2 raw = *reinterpret_cast<const uint2*>(Wh + base);
    float2 w01 = __half22float2(*reinterpret_cast<__half2*>(&raw.x));
    float2 w23 = __half22float2(*reinterpret_cast<__half2*>(&raw.y));
    float4 d4 = *reinterpret_cast<const float4*>(dots + b * CC + c);
    const float spv = sumpi[b * HH + h] + 1e-8f;
    const float p = -pi[(size_t)m * HH + h];
    float a0 = 1.0f / (1.0f + d4.x / spv);
    float a1 = 1.0f / (1.0f + d4.y / spv);
    float a2 = 1.0f / (1.0f + d4.z / spv);
    float a3 = 1.0f / (1.0f + d4.w / spv);
    __half2 o[2];
    o[0] = __halves2half2(__float2half_rn(w01.x * p * a0),
                          __float2half_rn(w01.y * p * a1));
    o[1] = __halves2half2(__float2half_rn(w23.x * p * a2),
                          __float2half_rn(w23.y * p * a3));
    reinterpret_cast<uint2*>(Th)[idx] = *reinterpret_cast<uint2*>(o);
}

// ---------------- launch ---------------------------------------------------
extern "C" void kernel_launch(void* const* d_in, const int* in_sizes, int n_in,
                              void* d_out, int out_size)
{
    const float* x     = (const float*)d_in[0];
    const float* qkv_w = (const float*)d_in[1];
    const float* temp  = (const float*)d_in[2];
    const float* out_w = (const float*)d_in[3];
    const float* out_b = (const float*)d_in[4];
    float* y = (float*)d_out;

    float *pi, *stats;
    __half *Wh, *Ah, *B1, *B2;
    cudaGetSymbolAddress((void**)&Wh,    g_Wh);
    cudaGetSymbolAddress((void**)&pi,    g_pi);
    cudaGetSymbolAddress((void**)&stats, g_stats);
    cudaGetSymbolAddress((void**)&Ah,    g_Ah);
    cudaGetSymbolAddress((void**)&B1,    g_B1);
    cudaGetSymbolAddress((void**)&B2,    g_B2);
    float* nrm  = stats;
    float* dots = stats + BB * CC;
    float* sp   = stats + 2 * BB * CC;

    cudaFuncSetAttribute(gemm_fp16, cudaFuncAttributeMaxDynamicSharedMemorySize, NSTG * STG_BYTES);

    cudaMemsetAsync(stats, 0, (2 * BB * CC + BB * HH) * sizeof(float));

    const int n4_big   = (MM * CC) / 4;
    const int n4_small = (CC * CC) / 4;

    cast_fp16_kernel<<<n4_big / 256, 256>>>(x, Ah, n4_big);
    cast_fp16_kernel<<<n4_small / 256, 256>>>(qkv_w, B1, n4_small);
    cast_fp16_kernel<<<n4_small / 256, 256>>>(out_w, B2, n4_small);

    dim3 ggrid(CC / 128, MM / 128);   // (8, 128)

    // 1) W = x @ qkv_w^T (fp16 HMMA) -> fp16 W + fused norm2
    gemm_fp16<<<ggrid, 256, NSTG * STG_BYTES>>>(Ah, B1, nullptr, nullptr, Wh, nrm, MM, CC, CC);
    // 2) stats
    pi_kernel<<<MM / 16, 256>>>(Wh, nrm, temp, pi, dots, sp);
    // 3) gate (attn fused) -> fp16 (reuses Ah)
    gate_kernel<<<(int)(((size_t)MM * CC / 4) / 256), 256>>>(Wh, pi, dots, sp, Ah);
    // 4) y = T @ out_w^T + out_b (fp32 out)
    gemm_fp16<<<ggrid, 256, NSTG * STG_BYTES>>>(Ah, B2, out_b, y, nullptr, nullptr, MM, CC, CC);
}

// round 14
// speedup vs baseline: 1.6447x; 1.0675x over previous
#include <cuda_runtime.h>
#include <cuda_fp16.h>
#include <cstdint>
#include <math.h>

// Problem constants
#define BB 4
#define NN 4096
#define CC 1024
#define HH 16
#define MM (BB*NN)   // 16384

// ---------------- scratch (device globals; no allocation) ----------------
__device__ __half g_Wh[(size_t)MM * CC];     // qkv projection result fp16
__device__ __half g_Ah[(size_t)MM * CC];     // fp16 of x, later of T
__device__ __half g_B1[(size_t)CC * CC];     // qkv_w fp16
__device__ __half g_B2[(size_t)CC * CC];     // out_w fp16
__device__ float g_pi[(size_t)MM * HH];
// stats: [0,BB*CC) = norm2, [BB*CC,2*BB*CC) = dots, [2*BB*CC,+BB*HH) = sumpi
__device__ float g_stats[2 * BB * CC + BB * HH];

// ---------------- PTX helpers ---------------------------------------------
__device__ __forceinline__ uint32_t smem_u32(const void* p) {
    uint32_t a;
    asm("{ .reg .u64 t; cvta.to.shared.u64 t, %1; cvt.u32.u64 %0, t; }" : "=r"(a) : "l"(p));
    return a;
}
#define CP_ASYNC16(dst, src) \
    asm volatile("cp.async.cg.shared.global [%0], [%1], 16;" :: "r"(dst), "l"(src) : "memory")
#define CP_COMMIT() asm volatile("cp.async.commit_group;" ::: "memory")
#define CP_WAIT2()  asm volatile("cp.async.wait_group 2;" ::: "memory")

__device__ __forceinline__ void ldsm4(uint32_t* r, uint32_t addr) {
    asm volatile("ldmatrix.sync.aligned.m8n8.x4.shared.b16 {%0,%1,%2,%3}, [%4];"
        : "=r"(r[0]), "=r"(r[1]), "=r"(r[2]), "=r"(r[3]) : "r"(addr));
}
__device__ __forceinline__ void mma16816(float* c, const uint32_t* a, const uint32_t* b) {
    asm volatile("mma.sync.aligned.m16n8k16.row.col.f32.f16.f16.f32 "
        "{%0,%1,%2,%3}, {%4,%5,%6,%7}, {%8,%9}, {%0,%1,%2,%3};"
        : "+f"(c[0]), "+f"(c[1]), "+f"(c[2]), "+f"(c[3])
        : "r"(a[0]), "r"(a[1]), "r"(a[2]), "r"(a[3]), "r"(b[0]), "r"(b[1]));
}

// smem tile: 128 rows x 32 fp16 (64B/row). Swizzle 16B chunks by ((row>>1)&3)<<4.
__device__ __forceinline__ uint32_t tswz(int row, int kb) {
    return (uint32_t)(row * 64 + (kb ^ (((row >> 1) & 3) << 4)));
}

// ---------------- fp16 HMMA GEMM: C[m,n] = sum_k A[m,k]*B[n,k] (+bias) ----
// Tile 128x128, BK=32, 256 threads (warps 2m x 4n, 64x32 each), 4-stage pipe.
// 2 CTAs/SM (regs capped at 128, 64KB smem per CTA).
// Output: fp32 (Cf, with bias) OR fp16 (Ch) — exactly one non-null.
#define STG_BYTES 16384     // 2 sub-tiles x 8KB per stage
#define OFF_A  0
#define OFF_B  8192
#define NSTG 4

__global__ __launch_bounds__(256, 2) void gemm_fp16(
    const __half* __restrict__ A, const __half* __restrict__ B,
    const float* __restrict__ bias, float* __restrict__ Cf,
    __half* __restrict__ Ch, float* __restrict__ norm2,
    int M, int N, int K)
{
    extern __shared__ __align__(1024) char smem[];
    const uint32_t sm_base = smem_u32(smem);

    const int tid  = threadIdx.x;
    const int lane = tid & 31;
    const int wid  = tid >> 5;
    const int mw   = wid >> 2;        // 0..1
    const int nw   = wid & 3;         // 0..3
    const int m0   = blockIdx.y * 128;
    const int n0   = blockIdx.x * 128;

    // ---- loader mapping: thread -> (row, 16B chunk) -----------------------
    const int lrow = tid >> 2;        // 0..63
    const int lk16 = tid & 3;         // 0..3
    const uint32_t dst_off0 = tswz(lrow,      lk16 * 16);
    const uint32_t dst_off1 = tswz(lrow + 64, lk16 * 16);
    const char* srcA0 = (const char*)(A + (size_t)(m0 + lrow)      * K) + lk16 * 16;
    const char* srcA1 = (const char*)(A + (size_t)(m0 + lrow + 64) * K) + lk16 * 16;
    const char* srcB0 = (const char*)(B + (size_t)(n0 + lrow)      * K) + lk16 * 16;
    const char* srcB1 = (const char*)(B + (size_t)(n0 + lrow + 64) * K) + lk16 * 16;

    const int NCHUNK = K / 32;        // 32

    auto load_stage = [&](int s) {
        const uint32_t sb = sm_base + (uint32_t)(s & (NSTG - 1)) * STG_BYTES;
        const int kb = s * 64;        // byte offset along K
        CP_ASYNC16(sb + OFF_A + dst_off0, srcA0 + kb);
        CP_ASYNC16(sb + OFF_A + dst_off1, srcA1 + kb);
        CP_ASYNC16(sb + OFF_B + dst_off0, srcB0 + kb);
        CP_ASYNC16(sb + OFF_B + dst_off1, srcB1 + kb);
        CP_COMMIT();
    };

    // ---- per-warp ldmatrix address components -----------------------------
    uint32_t a_row_off[4];
    #pragma unroll
    for (int mi = 0; mi < 4; mi++) {
        int row = mw * 64 + mi * 16 + (lane & 15);
        a_row_off[mi] = (uint32_t)(row * 64);
        a_row_off[mi] |= ((uint32_t)(((row >> 1) & 3) << 4)) << 16;
    }
    const uint32_t a_kb_lane = (uint32_t)((lane >> 4) << 4);
    uint32_t b_row_off[2];
    #pragma unroll
    for (int g = 0; g < 2; g++) {
        int row = nw * 32 + g * 16 + (lane & 7) + ((lane >> 4) << 3);
        b_row_off[g] = (uint32_t)(row * 64);
        b_row_off[g] |= ((uint32_t)(((row >> 1) & 3) << 4)) << 16;
    }
    const uint32_t b_kb_lane = (uint32_t)((lane & 8) << 1);

    float acc[4][4][4];
    #pragma unroll
    for (int i = 0; i < 4; i++)
        #pragma unroll
        for (int j = 0; j < 4; j++)
            #pragma unroll
            for (int q = 0; q < 4; q++) acc[i][j][q] = 0.f;

    load_stage(0);
    load_stage(1);
    load_stage(2);

    for (int s = 0; s < NCHUNK; s++) {
        CP_WAIT2();
        __syncthreads();
        const uint32_t sb = sm_base + (uint32_t)(s & (NSTG - 1)) * STG_BYTES;

        #pragma unroll
        for (int ks = 0; ks < 2; ks++) {
            const uint32_t akb = (uint32_t)(ks * 32) + a_kb_lane;
            const uint32_t bkb = (uint32_t)(ks * 32) + b_kb_lane;
            uint32_t fA[4][4], fB[2][4];
            #pragma unroll
            for (int mi = 0; mi < 4; mi++) {
                uint32_t ro = a_row_off[mi] & 0xFFFFu;
                uint32_t sw = a_row_off[mi] >> 16;
                ldsm4(fA[mi], sb + OFF_A + ro + (akb ^ sw));
            }
            #pragma unroll
            for (int g = 0; g < 2; g++) {
                uint32_t ro = b_row_off[g] & 0xFFFFu;
                uint32_t sw = b_row_off[g] >> 16;
                ldsm4(fB[g], sb + OFF_B + ro + (bkb ^ sw));
            }
            #pragma unroll
            for (int mi = 0; mi < 4; mi++) {
                #pragma unroll
                for (int nj = 0; nj < 4; nj++) {
                    mma16816(acc[mi][nj], fA[mi], &fB[nj >> 1][(nj & 1) * 2]);
                }
            }
        }
        if (s + 3 < NCHUNK) load_stage(s + 3);
        else CP_COMMIT();   // keep group count invariant for the tail waits
    }

    // ---- epilogue ---------------------------------------------------------
    const int mbase = m0 + mw * 64 + (lane >> 2);
    const int nbase = n0 + nw * 32 + 2 * (lane & 3);
    if (Ch) {
        #pragma unroll
        for (int mi = 0; mi < 4; mi++) {
            #pragma unroll
            for (int nj = 0; nj < 4; nj++) {
                const int r0 = mbase + mi * 16;
                const int cc = nbase + nj * 8;
                __half2 v0 = __floats2half2_rn(acc[mi][nj][0], acc[mi][nj][1]);
                __half2 v1 = __floats2half2_rn(acc[mi][nj][2], acc[mi][nj][3]);
                *reinterpret_cast<__half2*>(Ch + (size_t)r0 * N + cc)       = v0;
                *reinterpret_cast<__half2*>(Ch + (size_t)(r0 + 8) * N + cc) = v1;
            }
        }
    } else {
        #pragma unroll
        for (int mi = 0; mi < 4; mi++) {
            #pragma unroll
            for (int nj = 0; nj < 4; nj++) {
                const int r0 = mbase + mi * 16;
                const int cc = nbase + nj * 8;
                float b0 = 0.f, b1 = 0.f;
                if (bias) { b0 = __ldg(bias + cc); b1 = __ldg(bias + cc + 1); }
                float2 v0 = make_float2(acc[mi][nj][0] + b0, acc[mi][nj][1] + b1);
                float2 v1 = make_float2(acc[mi][nj][2] + b0, acc[mi][nj][3] + b1);
                *reinterpret_cast<float2*>(Cf + (size_t)r0 * N + cc)       = v0;
                *reinterpret_cast<float2*>(Cf + (size_t)(r0 + 8) * N + cc) = v1;
            }
        }
    }

    // ---- fused norm2: sum over this tile's 128 rows of C^2 per column -----
    if (norm2) {
        const int b = m0 >> 12;   // tile fits inside one batch (NN % 128 == 0)
        float cs[4][2];
        #pragma unroll
        for (int nj = 0; nj < 4; nj++) {
            cs[nj][0] = 0.f; cs[nj][1] = 0.f;
            #pragma unroll
            for (int mi = 0; mi < 4; mi++) {
                cs[nj][0] = fmaf(acc[mi][nj][0], acc[mi][nj][0], cs[nj][0]);
                cs[nj][0] = fmaf(acc[mi][nj][2], acc[mi][nj][2], cs[nj][0]);
                cs[nj][1] = fmaf(acc[mi][nj][1], acc[mi][nj][1], cs[nj][1]);
                cs[nj][1] = fmaf(acc[mi][nj][3], acc[mi][nj][3], cs[nj][1]);
            }
        }
        #pragma unroll
        for (int nj = 0; nj < 4; nj++) {
            #pragma unroll
            for (int t = 0; t < 2; t++) {
                float v = cs[nj][t];
                v += __shfl_xor_sync(0xffffffffu, v, 4);
                v += __shfl_xor_sync(0xffffffffu, v, 8);
                v += __shfl_xor_sync(0xffffffffu, v, 16);
                cs[nj][t] = v;
            }
        }
        if (lane < 4) {
            const int cb = n0 + nw * 32 + 2 * lane;
            #pragma unroll
            for (int nj = 0; nj < 4; nj++) {
                atomicAdd(&norm2[b * CC + cb + nj * 8],     cs[nj][0]);
                atomicAdd(&norm2[b * CC + cb + nj * 8 + 1], cs[nj][1]);
            }
        }
    }
}

// ---------------- fp32 -> fp16 cast ----------------------------------------
__global__ __launch_bounds__(256) void cast_fp16_kernel(
    const float* __restrict__ src, __half* __restrict__ dst, int n4)
{
    const int i = blockIdx.x * 256 + threadIdx.x;
    if (i >= n4) return;
    float4 v = reinterpret_cast<const float4*>(src)[i];
    __half2 h[2];
    h[0] = __halves2half2(__float2half_rn(v.x), __float2half_rn(v.y));
    h[1] = __halves2half2(__float2half_rn(v.z), __float2half_rn(v.w));
    reinterpret_cast<uint2*>(dst)[i] = *reinterpret_cast<uint2*>(h);
}

// ---------------- pi + reductions: warp-per-token --------------------------
// 256 blocks x 256 threads (8 warps). Each warp owns 8 tokens. Lane l, chunk
// i: 16B (8 halves) at chunk index i*32+l -> head = i*4 + (l>>3). Softmax
// over the 16 heads via octet-shfl + butterfly(8,16). dots accumulated in
// registers across tokens, flushed once via smem + global atomics.
__global__ __launch_bounds__(256) void pi_kernel(
    const __half* __restrict__ Wh, const float* __restrict__ norm2,
    const float* __restrict__ temp,
    float* __restrict__ pi_out, float* __restrict__ dots,
    float* __restrict__ sumpi)
{
    __shared__ float sdots[CC];
    const int tid   = threadIdx.x;
    const int lane  = tid & 31;
    const int w     = tid >> 5;
    const int oct   = lane >> 3;
    const int batch = blockIdx.x >> 6;          // 64 blocks per batch
    const int tokb  = (blockIdx.x & 63) * 64;   // 64 tokens per block

    #pragma unroll
    for (int k = 0; k < 4; k++) sdots[tid * 4 + k] = 0.f;

    // per-lane inv normalizer squared, for the lane's 32 columns
    float inv2[4][8];
    float tmult[4];
    #pragma unroll
    for (int i = 0; i < 4; i++) {
        const float* np = norm2 + batch * CC + (i * 32 + lane) * 8;
        float4 v0 = *reinterpret_cast<const float4*>(np);
        float4 v1 = *reinterpret_cast<const float4*>(np + 4);
        float vv[8] = {v0.x, v0.y, v0.z, v0.w, v1.x, v1.y, v1.z, v1.w};
        #pragma unroll
        for (int j = 0; j < 8; j++) {
            float inv = 1.0f / fmaxf(sqrtf(vv[j]), 1e-12f);
            inv2[i][j] = inv * inv;
        }
        tmult[i] = __ldg(temp + i * 4 + oct);
    }
    __syncthreads();

    float accD[4][8];
    #pragma unroll
    for (int i = 0; i < 4; i++)
        #pragma unroll
        for (int j = 0; j < 8; j++) accD[i][j] = 0.f;
    float sumPiLoc[4] = {0.f, 0.f, 0.f, 0.f};

    for (int t = 0; t < 8; t++) {
        const size_t m = (size_t)batch * NN + tokb + w * 8 + t;
        const uint4* row = reinterpret_cast<const uint4*>(Wh + m * CC);
        float sq[4][8];
        float s[4];
        #pragma unroll
        for (int i = 0; i < 4; i++) {
            uint4 raw = row[i * 32 + lane];
            float2 f0 = __half22float2(*reinterpret_cast<__half2*>(&raw.x));
            float2 f1 = __half22float2(*reinterpret_cast<__half2*>(&raw.y));
            float2 f2 = __half22float2(*reinterpret_cast<__half2*>(&raw.z));
            float2 f3 = __half22float2(*reinterpret_cast<__half2*>(&raw.w));
            float f[8] = {f0.x, f0.y, f1.x, f1.y, f2.x, f2.y, f3.x, f3.y};
            float part = 0.f;
            #pragma unroll
            for (int j = 0; j < 8; j++) {
                sq[i][j] = f[j] * f[j];
                part = fmaf(sq[i][j], inv2[i][j], part);
            }
            // reduce within the octet (8 lanes share head i*4+oct)
            part += __shfl_xor_sync(0xffffffffu, part, 1);
            part += __shfl_xor_sync(0xffffffffu, part, 2);
            part += __shfl_xor_sync(0xffffffffu, part, 4);
            s[i] = part * tmult[i];
        }
        // softmax over 16 heads: local max over i, butterfly across octets
        float mx = fmaxf(fmaxf(s[0], s[1]), fmaxf(s[2], s[3]));
        mx = fmaxf(mx, __shfl_xor_sync(0xffffffffu, mx, 8));
        mx = fmaxf(mx, __shfl_xor_sync(0xffffffffu, mx, 16));
        float e[4];
        float loc = 0.f;
        #pragma unroll
        for (int i = 0; i < 4; i++) { e[i] = expf(s[i] - mx); loc += e[i]; }
        loc += __shfl_xor_sync(0xffffffffu, loc, 8);
        loc += __shfl_xor_sync(0xffffffffu, loc, 16);
        const float rinv = 1.0f / loc;
        #pragma unroll
        for (int i = 0; i < 4; i++) {
            const float p = e[i] * rinv;
            if ((lane & 7) == 0) pi_out[m * HH + i * 4 + oct] = p;
            sumPiLoc[i] += p;
            #pragma unroll
            for (int j = 0; j < 8; j++)
                accD[i][j] = fmaf(p, sq[i][j], accD[i][j]);
        }
    }

    // flush dots: smem atomics (8-way warp contention, spread addresses)
    #pragma unroll
    for (int i = 0; i < 4; i++)
        #pragma unroll
        for (int j = 0; j < 8; j++)
            atomicAdd(&sdots[(i * 32 + lane) * 8 + j], accD[i][j]);
    __syncthreads();
    #pragma unroll
    for (int k = 0; k < 4; k++)
        atomicAdd(&dots[batch * CC + tid * 4 + k], sdots[tid * 4 + k]);
    if ((lane & 7) == 0) {
        #pragma unroll
        for (int i = 0; i < 4; i++)
            atomicAdd(&sumpi[batch * HH + i * 4 + oct], sumPiLoc[i]);
    }
}

// ---- gate (attn fused): T = -W * pi * (1/(1+dots/(sumpi+1e-8))) -> fp16 ---
__global__ __launch_bounds__(256) void gate_kernel(
    const __half* __restrict__ Wh, const float* __restrict__ pi,
    const float* __restrict__ dots, const float* __restrict__ sumpi,
    __half* __restrict__ Th)
{
    const size_t idx  = (size_t)blockIdx.x * 256 + threadIdx.x;
    const size_t base = idx * 4;
    const int m = (int)(base >> 10);
    const int c = (int)(base & (CC - 1));
    const int b = m >> 12;
    const int h = c >> 6;
    uint2 raw = *reinterpret_cast<const uint2*>(Wh + base);
    float2 w01 = __half22float2(*reinterpret_cast<__half2*>(&raw.x));
    float2 w23 = __half22float2(*reinterpret_cast<__half2*>(&raw.y));
    float4 d4 = *reinterpret_cast<const float4*>(dots + b * CC + c);
    const float spv = sumpi[b * HH + h] + 1e-8f;
    const float p = -pi[(size_t)m * HH + h];
    float a0 = 1.0f / (1.0f + d4.x / spv);
    float a1 = 1.0f / (1.0f + d4.y / spv);
    float a2 = 1.0f / (1.0f + d4.z / spv);
    float a3 = 1.0f / (1.0f + d4.w / spv);
    __half2 o[2];
    o[0] = __halves2half2(__float2half_rn(w01.x * p * a0),
                          __float2half_rn(w01.y * p * a1));
    o[1] = __halves2half2(__float2half_rn(w23.x * p * a2),
                          __float2half_rn(w23.y * p * a3));
    reinterpret_cast<uint2*>(Th)[idx] = *reinterpret_cast<uint2*>(o);
}

// ---------------- launch ---------------------------------------------------
extern "C" void kernel_launch(void* const* d_in, const int* in_sizes, int n_in,
                              void* d_out, int out_size)
{
    const float* x     = (const float*)d_in[0];
    const float* qkv_w = (const float*)d_in[1];
    const float* temp  = (const float*)d_in[2];
    const float* out_w = (const float*)d_in[3];
    const float* out_b = (const float*)d_in[4];
    float* y = (float*)d_out;

    float *pi, *stats;
    __half *Wh, *Ah, *B1, *B2;
    cudaGetSymbolAddress((void**)&Wh,    g_Wh);
    cudaGetSymbolAddress((void**)&pi,    g_pi);
    cudaGetSymbolAddress((void**)&stats, g_stats);
    cudaGetSymbolAddress((void**)&Ah,    g_Ah);
    cudaGetSymbolAddress((void**)&B1,    g_B1);
    cudaGetSymbolAddress((void**)&B2,    g_B2);
    float* nrm  = stats;
    float* dots = stats + BB * CC;
    float* sp   = stats + 2 * BB * CC;

    cudaFuncSetAttribute(gemm_fp16, cudaFuncAttributeMaxDynamicSharedMemorySize, NSTG * STG_BYTES);

    cudaMemsetAsync(stats, 0, (2 * BB * CC + BB * HH) * sizeof(float));

    const int n4_big   = (MM * CC) / 4;
    const int n4_small = (CC * CC) / 4;

    cast_fp16_kernel<<<n4_big / 256, 256>>>(x, Ah, n4_big);
    cast_fp16_kernel<<<n4_small / 256, 256>>>(qkv_w, B1, n4_small);
    cast_fp16_kernel<<<n4_small / 256, 256>>>(out_w, B2, n4_small);

    dim3 ggrid(CC / 128, MM / 128);   // (8, 128)

    // 1) W = x @ qkv_w^T (fp16 HMMA) -> fp16 W + fused norm2
    gemm_fp16<<<ggrid, 256, NSTG * STG_BYTES>>>(Ah, B1, nullptr, nullptr, Wh, nrm, MM, CC, CC);
    // 2) stats (warp-per-token)
    pi_kernel<<<256, 256>>>(Wh, nrm, temp, pi, dots, sp);
    // 3) gate (attn fused) -> fp16 (reuses Ah)
    gate_kernel<<<(int)(((size_t)MM * CC / 4) / 256), 256>>>(Wh, pi, dots, sp, Ah);
    // 4) y = T @ out_w^T + out_b (fp32 out)
    gemm_fp16<<<ggrid, 256, NSTG * STG_BYTES>>>(Ah, B2, out_b, y, nullptr, nullptr, MM, CC, CC);
}